// round 10
// baseline (speedup 1.0000x reference)
#include <cuda_runtime.h>

// out[j]     = dot(X[r1(j)], p), r1(j) = inds1[2j]*28 + inds1[2j+1], j in [0,100)
// out[100+j] = dot(Y[r2(j)], p)
// 100 CTAs x 512 threads (pair j: X-dot + Y-dot share the p loads).
// launch_bounds(512,1) -> 128-reg budget: four 12-load groups (4 p + 4 x + 4 y
// float4), software-pipelined 2-deep => up to 24 LDG.128 in flight per thread.

#define Q      32768
#define QV     (Q / 4)      // 8192 float4 per row
#define NT     512
#define W_DIM  28

__device__ __forceinline__ float dot4(float4 a, float4 b) {
    return a.x * b.x + a.y * b.y + a.z * b.z + a.w * b.w;
}

// load one group of 4 consecutive-stride float4 from each of p, X-row, Y-row
#define LOAD_GROUP(g, base)                                            \
    float4 p##g##0 = pv  [(base)           ];                          \
    float4 p##g##1 = pv  [(base) +     NT  ];                          \
    float4 p##g##2 = pv  [(base) + 2 * NT  ];                          \
    float4 p##g##3 = pv  [(base) + 3 * NT  ];                          \
    float4 x##g##0 = rowX[(base)           ];                          \
    float4 x##g##1 = rowX[(base) +     NT  ];                          \
    float4 x##g##2 = rowX[(base) + 2 * NT  ];                          \
    float4 x##g##3 = rowX[(base) + 3 * NT  ];                          \
    float4 y##g##0 = rowY[(base)           ];                          \
    float4 y##g##1 = rowY[(base) +     NT  ];                          \
    float4 y##g##2 = rowY[(base) + 2 * NT  ];                          \
    float4 y##g##3 = rowY[(base) + 3 * NT  ];

#define CONSUME_GROUP(g)                                               \
    sumX += dot4(x##g##0, p##g##0);                                    \
    sumX += dot4(x##g##1, p##g##1);                                    \
    sumX += dot4(x##g##2, p##g##2);                                    \
    sumX += dot4(x##g##3, p##g##3);                                    \
    sumY += dot4(y##g##0, p##g##0);                                    \
    sumY += dot4(y##g##1, p##g##1);                                    \
    sumY += dot4(y##g##2, p##g##2);                                    \
    sumY += dot4(y##g##3, p##g##3);

__global__ __launch_bounds__(NT, 1)
void paired_dot_kernel(const float* __restrict__ X,
                       const float* __restrict__ Y,
                       const float* __restrict__ p,
                       const int*   __restrict__ inds1,
                       const int*   __restrict__ inds2,
                       float* __restrict__ out)
{
    const int j = blockIdx.x;            // 0..99

    const int r1 = inds1[2 * j] * W_DIM + inds1[2 * j + 1];
    const int r2 = inds2[2 * j] * W_DIM + inds2[2 * j + 1];

    const float4* __restrict__ pv   = reinterpret_cast<const float4*>(p);
    const float4* __restrict__ rowX = reinterpret_cast<const float4*>(X + (size_t)r1 * Q);
    const float4* __restrict__ rowY = reinterpret_cast<const float4*>(Y + (size_t)r2 * Q);

    const int t = threadIdx.x;           // 16 float4 per array per thread
    float sumX = 0.0f, sumY = 0.0f;

    // Software pipeline: keep 2 groups (24 LDG.128) in flight.
    LOAD_GROUP(A, t)                          // k = 0..3
    LOAD_GROUP(B, t + 4 * NT)                 // k = 4..7
    CONSUME_GROUP(A)
    LOAD_GROUP(C, t + 8 * NT)                 // k = 8..11
    CONSUME_GROUP(B)
    LOAD_GROUP(D, t + 12 * NT)                // k = 12..15
    CONSUME_GROUP(C)
    CONSUME_GROUP(D)

    // warp reduce both sums
    #pragma unroll
    for (int off = 16; off > 0; off >>= 1) {
        sumX += __shfl_xor_sync(0xFFFFFFFFu, sumX, off);
        sumY += __shfl_xor_sync(0xFFFFFFFFu, sumY, off);
    }

    __shared__ float warp_sums[NT / 32][2];
    const int lane = t & 31;
    const int wid  = t >> 5;
    if (lane == 0) {
        warp_sums[wid][0] = sumX;
        warp_sums[wid][1] = sumY;
    }
    __syncthreads();

    if (wid == 0) {
        float sx = (lane < NT / 32) ? warp_sums[lane][0] : 0.0f;
        float sy = (lane < NT / 32) ? warp_sums[lane][1] : 0.0f;
        #pragma unroll
        for (int off = 8; off > 0; off >>= 1) {
            sx += __shfl_xor_sync(0xFFFFFFFFu, sx, off);
            sy += __shfl_xor_sync(0xFFFFFFFFu, sy, off);
        }
        if (lane == 0) {
            out[j]       = sx;
            out[j + 100] = sy;
        }
    }
}

extern "C" void kernel_launch(void* const* d_in, const int* in_sizes, int n_in,
                              void* d_out, int out_size)
{
    const float* X   = (const float*)d_in[0];
    const float* Y   = (const float*)d_in[1];
    const float* p   = (const float*)d_in[2];
    const int* inds1 = (const int*)d_in[3];
    const int* inds2 = (const int*)d_in[4];
    float* out       = (float*)d_out;

    paired_dot_kernel<<<100, NT>>>(X, Y, p, inds1, inds2, out);
}